// round 2
// baseline (speedup 1.0000x reference)
#include <cuda_runtime.h>
#include <cstdint>

// Problem constants
#define T_SEQ 2048
#define EMB   2048
#define NH    32
#define HD    64

// -------- scratch (device globals; no allocation allowed) --------
__device__ float g_Q[T_SEQ * EMB];   // q projection [T, E] (head-interleaved h*64+d)
__device__ float g_K[T_SEQ * HD];    // k projection [T, 64]
__device__ float g_V[T_SEQ * HD];    // v projection [T, 64]
__device__ float g_A[T_SEQ * EMB];   // attention output [T, E]

// ============================================================
// GEMM:  C[M,N] = A[M,K] @ B[N,K]^T   (both K-contiguous, fp32)
// BM=BN=64, BK=16, 256 threads, 4x4 microtile per thread
// ============================================================
#define BM 64
#define BN 64
#define BK 16

__global__ __launch_bounds__(256) void gemm_nt(const float* __restrict__ A,
                                               const float* __restrict__ B,
                                               float* __restrict__ C,
                                               int M, int N, int K) {
    __shared__ float As[BM][BK + 1];
    __shared__ float Bs[BN][BK + 1];

    const int tid = threadIdx.x;
    const int tx = tid & 15;       // n-tile index 0..15
    const int ty = tid >> 4;       // m-tile index 0..15
    const int m0 = blockIdx.y * BM;
    const int n0 = blockIdx.x * BN;

    const int lr = tid >> 2;       // 0..63 load row
    const int lc = tid & 3;        // float4 column within BK

    float acc[4][4] = {};

    for (int k0 = 0; k0 < K; k0 += BK) {
        float4 av = *(const float4*)(A + (size_t)(m0 + lr) * K + k0 + lc * 4);
        float4 bv = *(const float4*)(B + (size_t)(n0 + lr) * K + k0 + lc * 4);
        As[lr][lc * 4 + 0] = av.x; As[lr][lc * 4 + 1] = av.y;
        As[lr][lc * 4 + 2] = av.z; As[lr][lc * 4 + 3] = av.w;
        Bs[lr][lc * 4 + 0] = bv.x; Bs[lr][lc * 4 + 1] = bv.y;
        Bs[lr][lc * 4 + 2] = bv.z; Bs[lr][lc * 4 + 3] = bv.w;
        __syncthreads();

#pragma unroll
        for (int k = 0; k < BK; k++) {
            float a[4], b[4];
#pragma unroll
            for (int i = 0; i < 4; i++) a[i] = As[ty * 4 + i][k];
#pragma unroll
            for (int j = 0; j < 4; j++) b[j] = Bs[tx * 4 + j][k];
#pragma unroll
            for (int i = 0; i < 4; i++)
#pragma unroll
                for (int j = 0; j < 4; j++)
                    acc[i][j] += a[i] * b[j];
        }
        __syncthreads();
    }

#pragma unroll
    for (int i = 0; i < 4; i++) {
        float* cp = C + (size_t)(m0 + ty * 4 + i) * N + n0 + tx * 4;
#pragma unroll
        for (int j = 0; j < 4; j++) cp[j] = acc[i][j];
    }
}

// ============================================================
// Flash attention, MQA (1 KV head), ALiBi + causal, fp32.
// Grid: (T/BQ, NH). Block: 256 threads.
// Each block: 128 query rows of one head. 2 threads per row,
// each owning 32 of 64 output dims; shfl_xor(1) combines dots.
// ============================================================
#define BQ 128
#define TK 64
#define CK 16

__global__ __launch_bounds__(256) void attn_kernel(const float* __restrict__ Q,
                                                   const float* __restrict__ Kg,
                                                   const float* __restrict__ Vg,
                                                   float* __restrict__ O) {
    const int h   = blockIdx.y;
    const int q0  = blockIdx.x * BQ;
    const int tid = threadIdx.x;
    const int row  = tid >> 1;          // 0..127
    const int half = tid & 1;           // 0/1 -> dims [half*32, half*32+32)
    const int i    = q0 + row;          // absolute query index
    const float slope = exp2f(-0.25f * (float)(h + 1));

    __shared__ float4 Ksh[TK][HD / 4];  // 16 KB
    __shared__ float4 Vsh[TK][HD / 4];  // 16 KB

    // load q row half, pre-scaled by D^-0.5
    float4 q4[8];
    {
        const float4* qp = (const float4*)(Q + (size_t)i * EMB + h * HD + half * 32);
#pragma unroll
        for (int r = 0; r < 8; r++) {
            float4 v = qp[r];
            v.x *= 0.125f; v.y *= 0.125f; v.z *= 0.125f; v.w *= 0.125f;
            q4[r] = v;
        }
    }

    float4 o4[8];
#pragma unroll
    for (int r = 0; r < 8; r++) o4[r] = make_float4(0.f, 0.f, 0.f, 0.f);
    float m = -1e30f;
    float l = 0.f;

    const int jmax = q0 + BQ;   // keys needed: j <= i <= q0+BQ-1

    for (int j0 = 0; j0 < jmax; j0 += TK) {
        __syncthreads();
        // stage K/V tile: 64 rows x 16 float4 each; 4 float4 per thread per tensor
#pragma unroll
        for (int u = 0; u < 4; u++) {
            int idx = tid + u * 256;         // 0..1023
            int kr = idx >> 4;
            int kc = idx & 15;
            Ksh[kr][kc] = ((const float4*)(Kg + (size_t)(j0 + kr) * HD))[kc];
            Vsh[kr][kc] = ((const float4*)(Vg + (size_t)(j0 + kr) * HD))[kc];
        }
        __syncthreads();

#pragma unroll
        for (int c = 0; c < TK / CK; c++) {
            float s[CK];
#pragma unroll
            for (int kk = 0; kk < CK; kk++) {
                const int k = c * CK + kk;
                const float4* kp = &Ksh[k][half * 8];
                float acc = 0.f;
#pragma unroll
                for (int r = 0; r < 8; r++) {
                    float4 kv = kp[r];
                    acc += q4[r].x * kv.x + q4[r].y * kv.y
                         + q4[r].z * kv.z + q4[r].w * kv.w;
                }
                acc += __shfl_xor_sync(0xffffffffu, acc, 1);
                const int j = j0 + k;
                s[kk] = (j <= i) ? (acc + slope * (float)(j - i)) : -10000.0f;
            }
            // chunk max
            float mc = s[0];
#pragma unroll
            for (int kk = 1; kk < CK; kk++) mc = fmaxf(mc, s[kk]);
            const float m_new = fmaxf(m, mc);
            const float alpha = __expf(m - m_new);
            float psum = 0.f;
#pragma unroll
            for (int kk = 0; kk < CK; kk++) {
                s[kk] = __expf(s[kk] - m_new);
                psum += s[kk];
            }
            l = l * alpha + psum;
#pragma unroll
            for (int r = 0; r < 8; r++) {
                o4[r].x *= alpha; o4[r].y *= alpha;
                o4[r].z *= alpha; o4[r].w *= alpha;
            }
#pragma unroll
            for (int kk = 0; kk < CK; kk++) {
                const float p = s[kk];
                const float4* vp = &Vsh[c * CK + kk][half * 8];
#pragma unroll
                for (int r = 0; r < 8; r++) {
                    float4 vv = vp[r];
                    o4[r].x += p * vv.x; o4[r].y += p * vv.y;
                    o4[r].z += p * vv.z; o4[r].w += p * vv.w;
                }
            }
            m = m_new;
        }
    }

    const float inv = 1.0f / l;
    float4* op = (float4*)(O + (size_t)i * EMB + h * HD + half * 32);
#pragma unroll
    for (int r = 0; r < 8; r++) {
        float4 v = o4[r];
        v.x *= inv; v.y *= inv; v.z *= inv; v.w *= inv;
        op[r] = v;
    }
}

// ============================================================
// launch
// ============================================================
extern "C" void kernel_launch(void* const* d_in, const int* in_sizes, int n_in,
                              void* d_out, int out_size) {
    (void)in_sizes; (void)n_in; (void)out_size;
    const float* x  = (const float*)d_in[0];   // [T, E]
    const float* Wq = (const float*)d_in[1];   // [E, E]
    const float* Wk = (const float*)d_in[2];   // [D, E]
    const float* Wv = (const float*)d_in[3];   // [D, E]
    const float* Wo = (const float*)d_in[4];   // [E, E]
    // d_in[5] = attention_mask (causal, known analytically) — ignored
    float* out = (float*)d_out;                // [T, E]

    void *pQ, *pK, *pV, *pA;
    cudaGetSymbolAddress(&pQ, g_Q);
    cudaGetSymbolAddress(&pK, g_K);
    cudaGetSymbolAddress(&pV, g_V);
    cudaGetSymbolAddress(&pA, g_A);
    float* Qd = (float*)pQ;
    float* Kd = (float*)pK;
    float* Vd = (float*)pV;
    float* Ad = (float*)pA;

    // Q projection: [T,E] = x @ Wq^T
    gemm_nt<<<dim3(EMB / BN, T_SEQ / BM), 256>>>(x, Wq, Qd, T_SEQ, EMB, EMB);
    // K projection: [T,64] = x @ Wk^T
    gemm_nt<<<dim3(HD / BN, T_SEQ / BM), 256>>>(x, Wk, Kd, T_SEQ, HD, EMB);
    // V projection: [T,64] = x @ Wv^T
    gemm_nt<<<dim3(HD / BN, T_SEQ / BM), 256>>>(x, Wv, Vd, T_SEQ, HD, EMB);
    // attention
    attn_kernel<<<dim3(T_SEQ / BQ, NH), 256>>>(Qd, Kd, Vd, Ad);
    // output projection: [T,E] = A @ Wo^T
    gemm_nt<<<dim3(EMB / BN, T_SEQ / BM), 256>>>(Ad, Wo, out, T_SEQ, EMB, EMB);
}

// round 4
// speedup vs baseline: 1.5910x; 1.5910x over previous
#include <cuda_runtime.h>
#include <cstdint>

// Problem constants
#define T_SEQ 2048
#define EMB   2048
#define NH    32
#define HD    64

// -------- scratch (device globals; no allocation allowed) --------
__device__ float g_Q[T_SEQ * EMB];   // q projection [T, E]
__device__ float g_K[T_SEQ * HD];    // k projection [T, 64]
__device__ float g_V[T_SEQ * HD];    // v projection [T, 64]
__device__ float g_A[T_SEQ * EMB];   // attention output [T, E]

// ============================================================
// helpers
// ============================================================
__device__ __forceinline__ uint32_t smem_u32(const void* p) {
    uint32_t a;
    asm("{ .reg .u64 t; cvta.to.shared.u64 t, %1; cvt.u32.u64 %0, t; }" : "=r"(a) : "l"(p));
    return a;
}
__device__ __forceinline__ uint32_t f2tf32(float x) {
    uint32_t r;
    asm("cvt.rna.tf32.f32 %0, %1;" : "=r"(r) : "f"(x));
    return r;
}
__device__ __forceinline__ void cp16(uint32_t dst, const void* src) {
    asm volatile("cp.async.cg.shared.global [%0], [%1], 16;" :: "r"(dst), "l"(src) : "memory");
}
__device__ __forceinline__ void mma_tf32(float& d0, float& d1, float& d2, float& d3,
                                         uint32_t a0, uint32_t a1, uint32_t a2, uint32_t a3,
                                         uint32_t b0, uint32_t b1) {
    asm volatile("mma.sync.aligned.m16n8k8.row.col.f32.tf32.tf32.f32 "
                 "{%0,%1,%2,%3}, {%4,%5,%6,%7}, {%8,%9}, {%0,%1,%2,%3};"
                 : "+f"(d0), "+f"(d1), "+f"(d2), "+f"(d3)
                 : "r"(a0), "r"(a1), "r"(a2), "r"(a3), "r"(b0), "r"(b1));
}

// ============================================================
// tf32 mma.sync GEMM:  C[M,N] = A[M,K] @ B[N,K]^T
// CTA 128x128, K-chunk 32, 8 warps (2m x 4n), warp tile 64x32.
// Double-buffered cp.async staging, padded smem (36 floats/row).
// dual mode: B rows 0-63 = B0 (Wk), 64-127 = B1 (Wv);
//            cols 0-63 -> C0 (ldc 64), cols 64-127 -> C1 (ldc 64).
// ============================================================
#define BKF 32
#define LDA 36
#define TILE_F (128 * LDA)                    // floats per operand tile
#define GEMM_SMEM (2 * 2 * TILE_F * 4)        // 73728 bytes

__global__ __launch_bounds__(256, 2) void gemm_tf32mma(
    const float* __restrict__ A, const float* __restrict__ B0,
    const float* __restrict__ B1, float* __restrict__ C0,
    float* __restrict__ C1, int K, int N, int dual) {
    extern __shared__ float sm[];
    const int tid  = threadIdx.x;
    const int wid  = tid >> 5;
    const int lane = tid & 31;
    const int wm   = wid & 1;          // warp row (0..1) -> 64 rows
    const int wn   = wid >> 1;         // warp col (0..3) -> 32 cols
    const int m0   = blockIdx.y * 128;
    const int n0   = blockIdx.x * 128;
    const int g    = lane >> 2;        // group id 0..7
    const int tig  = lane & 3;         // thread in group

    float acc[4][4][4];
#pragma unroll
    for (int i = 0; i < 4; i++)
#pragma unroll
        for (int j = 0; j < 4; j++)
#pragma unroll
            for (int r = 0; r < 4; r++) acc[i][j][r] = 0.f;

    const int NT = K / BKF;

    auto stage = [&](int t, int b) {
        float* dstA = sm + b * 2 * TILE_F;
        float* dstB = dstA + TILE_F;
#pragma unroll
        for (int u = 0; u < 4; u++) {
            int idx = u * 256 + tid;         // 0..1023 float4 slots
            int r = idx >> 3, c4 = idx & 7;
            cp16(smem_u32(dstA + r * LDA + c4 * 4),
                 A + (size_t)(m0 + r) * K + t * BKF + c4 * 4);
            const float* gb;
            if (dual) gb = (r < 64 ? B0 + (size_t)r * K : B1 + (size_t)(r - 64) * K)
                           + t * BKF + c4 * 4;
            else      gb = B0 + (size_t)(n0 + r) * K + t * BKF + c4 * 4;
            cp16(smem_u32(dstB + r * LDA + c4 * 4), gb);
        }
        asm volatile("cp.async.commit_group;" ::: "memory");
    };

    stage(0, 0);

    for (int t = 0; t < NT; t++) {
        if (t + 1 < NT) {
            stage(t + 1, (t + 1) & 1);
            asm volatile("cp.async.wait_group 1;" ::: "memory");
        } else {
            asm volatile("cp.async.wait_group 0;" ::: "memory");
        }
        __syncthreads();

        const float* sA = sm + (t & 1) * 2 * TILE_F + (wm * 64) * LDA;
        const float* sB = sm + (t & 1) * 2 * TILE_F + TILE_F + (wn * 32) * LDA;

#pragma unroll
        for (int ks = 0; ks < 4; ks++) {
            uint32_t bf[4][2];
#pragma unroll
            for (int nt = 0; nt < 4; nt++) {
                const float* bp = sB + (nt * 8 + g) * LDA + ks * 8 + tig;
                bf[nt][0] = f2tf32(bp[0]);
                bf[nt][1] = f2tf32(bp[4]);
            }
            uint32_t af[4][4];
#pragma unroll
            for (int mt = 0; mt < 4; mt++) {
                const float* ap = sA + (mt * 16 + g) * LDA + ks * 8 + tig;
                af[mt][0] = f2tf32(ap[0]);
                af[mt][1] = f2tf32(ap[8 * LDA]);
                af[mt][2] = f2tf32(ap[4]);
                af[mt][3] = f2tf32(ap[8 * LDA + 4]);
            }
#pragma unroll
            for (int mt = 0; mt < 4; mt++)
#pragma unroll
                for (int nt = 0; nt < 4; nt++)
                    mma_tf32(acc[mt][nt][0], acc[mt][nt][1], acc[mt][nt][2], acc[mt][nt][3],
                             af[mt][0], af[mt][1], af[mt][2], af[mt][3],
                             bf[nt][0], bf[nt][1]);
        }
        __syncthreads();
    }

    // ---- epilogue ----
#pragma unroll
    for (int mt = 0; mt < 4; mt++) {
        const int row0 = m0 + wm * 64 + mt * 16 + g;
#pragma unroll
        for (int nt = 0; nt < 4; nt++) {
            const int colL = wn * 32 + nt * 8 + 2 * tig;   // local col within 128
            if (dual) {
                float* dst = (colL < 64) ? C0 : C1;
                const int c = (colL < 64) ? colL : colL - 64;
                *(float2*)(dst + (size_t)row0 * 64 + c)       = make_float2(acc[mt][nt][0], acc[mt][nt][1]);
                *(float2*)(dst + (size_t)(row0 + 8) * 64 + c) = make_float2(acc[mt][nt][2], acc[mt][nt][3]);
            } else {
                const int col = n0 + colL;
                *(float2*)(C0 + (size_t)row0 * N + col)       = make_float2(acc[mt][nt][0], acc[mt][nt][1]);
                *(float2*)(C0 + (size_t)(row0 + 8) * N + col) = make_float2(acc[mt][nt][2], acc[mt][nt][3]);
            }
        }
    }
}

// ============================================================
// Flash attention, MQA (1 KV head), ALiBi + causal, fp32.
// (unchanged — rework next round with a real profile)
// ============================================================
#define BQ 128
#define TK 64
#define CK 16

__global__ __launch_bounds__(256) void attn_kernel(const float* __restrict__ Q,
                                                   const float* __restrict__ Kg,
                                                   const float* __restrict__ Vg,
                                                   float* __restrict__ O) {
    const int h   = blockIdx.y;
    const int q0  = blockIdx.x * BQ;
    const int tid = threadIdx.x;
    const int row  = tid >> 1;
    const int half = tid & 1;
    const int i    = q0 + row;
    const float slope = exp2f(-0.25f * (float)(h + 1));

    __shared__ float4 Ksh[TK][HD / 4];
    __shared__ float4 Vsh[TK][HD / 4];

    float4 q4[8];
    {
        const float4* qp = (const float4*)(Q + (size_t)i * EMB + h * HD + half * 32);
#pragma unroll
        for (int r = 0; r < 8; r++) {
            float4 v = qp[r];
            v.x *= 0.125f; v.y *= 0.125f; v.z *= 0.125f; v.w *= 0.125f;
            q4[r] = v;
        }
    }

    float4 o4[8];
#pragma unroll
    for (int r = 0; r < 8; r++) o4[r] = make_float4(0.f, 0.f, 0.f, 0.f);
    float m = -1e30f;
    float l = 0.f;

    const int jmax = q0 + BQ;

    for (int j0 = 0; j0 < jmax; j0 += TK) {
        __syncthreads();
#pragma unroll
        for (int u = 0; u < 4; u++) {
            int idx = tid + u * 256;
            int kr = idx >> 4;
            int kc = idx & 15;
            Ksh[kr][kc] = ((const float4*)(Kg + (size_t)(j0 + kr) * HD))[kc];
            Vsh[kr][kc] = ((const float4*)(Vg + (size_t)(j0 + kr) * HD))[kc];
        }
        __syncthreads();

#pragma unroll
        for (int c = 0; c < TK / CK; c++) {
            float s[CK];
#pragma unroll
            for (int kk = 0; kk < CK; kk++) {
                const int k = c * CK + kk;
                const float4* kp = &Ksh[k][half * 8];
                float acc = 0.f;
#pragma unroll
                for (int r = 0; r < 8; r++) {
                    float4 kv = kp[r];
                    acc += q4[r].x * kv.x + q4[r].y * kv.y
                         + q4[r].z * kv.z + q4[r].w * kv.w;
                }
                acc += __shfl_xor_sync(0xffffffffu, acc, 1);
                const int j = j0 + k;
                s[kk] = (j <= i) ? (acc + slope * (float)(j - i)) : -10000.0f;
            }
            float mc = s[0];
#pragma unroll
            for (int kk = 1; kk < CK; kk++) mc = fmaxf(mc, s[kk]);
            const float m_new = fmaxf(m, mc);
            const float alpha = __expf(m - m_new);
            float psum = 0.f;
#pragma unroll
            for (int kk = 0; kk < CK; kk++) {
                s[kk] = __expf(s[kk] - m_new);
                psum += s[kk];
            }
            l = l * alpha + psum;
#pragma unroll
            for (int r = 0; r < 8; r++) {
                o4[r].x *= alpha; o4[r].y *= alpha;
                o4[r].z *= alpha; o4[r].w *= alpha;
            }
#pragma unroll
            for (int kk = 0; kk < CK; kk++) {
                const float p = s[kk];
                const float4* vp = &Vsh[c * CK + kk][half * 8];
#pragma unroll
                for (int r = 0; r < 8; r++) {
                    float4 vv = vp[r];
                    o4[r].x += p * vv.x; o4[r].y += p * vv.y;
                    o4[r].z += p * vv.z; o4[r].w += p * vv.w;
                }
            }
            m = m_new;
        }
    }

    const float inv = 1.0f / l;
    float4* op = (float4*)(O + (size_t)i * EMB + h * HD + half * 32);
#pragma unroll
    for (int r = 0; r < 8; r++) {
        float4 v = o4[r];
        v.x *= inv; v.y *= inv; v.z *= inv; v.w *= inv;
        op[r] = v;
    }
}

// ============================================================
// launch
// ============================================================
extern "C" void kernel_launch(void* const* d_in, const int* in_sizes, int n_in,
                              void* d_out, int out_size) {
    (void)in_sizes; (void)n_in; (void)out_size;
    const float* x  = (const float*)d_in[0];   // [T, E]
    const float* Wq = (const float*)d_in[1];   // [E, E]
    const float* Wk = (const float*)d_in[2];   // [D, E]
    const float* Wv = (const float*)d_in[3];   // [D, E]
    const float* Wo = (const float*)d_in[4];   // [E, E]
    float* out = (float*)d_out;                // [T, E]

    void *pQ, *pK, *pV, *pA;
    cudaGetSymbolAddress(&pQ, g_Q);
    cudaGetSymbolAddress(&pK, g_K);
    cudaGetSymbolAddress(&pV, g_V);
    cudaGetSymbolAddress(&pA, g_A);
    float* Qd = (float*)pQ;
    float* Kd = (float*)pK;
    float* Vd = (float*)pV;
    float* Ad = (float*)pA;

    cudaFuncSetAttribute(gemm_tf32mma, cudaFuncAttributeMaxDynamicSharedMemorySize, GEMM_SMEM);

    // Q projection: [T,E] = x @ Wq^T
    gemm_tf32mma<<<dim3(EMB / 128, T_SEQ / 128), 256, GEMM_SMEM>>>(
        x, Wq, nullptr, Qd, nullptr, EMB, EMB, 0);
    // K and V projections fused: B rows 0-63 = Wk, 64-127 = Wv
    gemm_tf32mma<<<dim3(1, T_SEQ / 128), 256, GEMM_SMEM>>>(
        x, Wk, Wv, Kd, Vd, EMB, 128, 1);
    // attention
    attn_kernel<<<dim3(T_SEQ / BQ, NH), 256>>>(Qd, Kd, Vd, Ad);
    // output projection: [T,E] = A @ Wo^T
    gemm_tf32mma<<<dim3(EMB / 128, T_SEQ / 128), 256, GEMM_SMEM>>>(
        Ad, Wo, nullptr, out, nullptr, EMB, EMB, 0);
}

// round 5
// speedup vs baseline: 4.5467x; 2.8577x over previous
#include <cuda_runtime.h>
#include <cstdint>

// Problem constants
#define T_SEQ 2048
#define EMB   2048
#define NH    32
#define HD    64

// -------- scratch (device globals; no allocation allowed) --------
__device__ float g_Q[T_SEQ * EMB];   // q projection [T, E]
__device__ float g_K[T_SEQ * HD];    // k projection [T, 64]
__device__ float g_V[T_SEQ * HD];    // v projection [T, 64]
__device__ float g_A[T_SEQ * EMB];   // attention output [T, E]

// ============================================================
// helpers
// ============================================================
__device__ __forceinline__ uint32_t smem_u32(const void* p) {
    uint32_t a;
    asm("{ .reg .u64 t; cvta.to.shared.u64 t, %1; cvt.u32.u64 %0, t; }" : "=r"(a) : "l"(p));
    return a;
}
__device__ __forceinline__ uint32_t f2tf32(float x) {
    uint32_t r;
    asm("cvt.rna.tf32.f32 %0, %1;" : "=r"(r) : "f"(x));
    return r;
}
__device__ __forceinline__ void cp16(uint32_t dst, const void* src) {
    asm volatile("cp.async.cg.shared.global [%0], [%1], 16;" :: "r"(dst), "l"(src) : "memory");
}
__device__ __forceinline__ void mma_tf32(float& d0, float& d1, float& d2, float& d3,
                                         uint32_t a0, uint32_t a1, uint32_t a2, uint32_t a3,
                                         uint32_t b0, uint32_t b1) {
    asm volatile("mma.sync.aligned.m16n8k8.row.col.f32.tf32.tf32.f32 "
                 "{%0,%1,%2,%3}, {%4,%5,%6,%7}, {%8,%9}, {%0,%1,%2,%3};"
                 : "+f"(d0), "+f"(d1), "+f"(d2), "+f"(d3)
                 : "r"(a0), "r"(a1), "r"(a2), "r"(a3), "r"(b0), "r"(b1));
}

// ============================================================
// tf32 mma.sync GEMM:  C[M,N] = A[M,K] @ B[N,K]^T   (unchanged from R4)
// ============================================================
#define BKF 32
#define LDA 36
#define TILE_F (128 * LDA)
#define GEMM_SMEM (2 * 2 * TILE_F * 4)

__global__ __launch_bounds__(256, 2) void gemm_tf32mma(
    const float* __restrict__ A, const float* __restrict__ B0,
    const float* __restrict__ B1, float* __restrict__ C0,
    float* __restrict__ C1, int K, int N, int dual) {
    extern __shared__ float sm[];
    const int tid  = threadIdx.x;
    const int wid  = tid >> 5;
    const int lane = tid & 31;
    const int wm   = wid & 1;
    const int wn   = wid >> 1;
    const int m0   = blockIdx.y * 128;
    const int n0   = blockIdx.x * 128;
    const int g    = lane >> 2;
    const int tig  = lane & 3;

    float acc[4][4][4];
#pragma unroll
    for (int i = 0; i < 4; i++)
#pragma unroll
        for (int j = 0; j < 4; j++)
#pragma unroll
            for (int r = 0; r < 4; r++) acc[i][j][r] = 0.f;

    const int NT = K / BKF;

    auto stage = [&](int t, int b) {
        float* dstA = sm + b * 2 * TILE_F;
        float* dstB = dstA + TILE_F;
#pragma unroll
        for (int u = 0; u < 4; u++) {
            int idx = u * 256 + tid;
            int r = idx >> 3, c4 = idx & 7;
            cp16(smem_u32(dstA + r * LDA + c4 * 4),
                 A + (size_t)(m0 + r) * K + t * BKF + c4 * 4);
            const float* gb;
            if (dual) gb = (r < 64 ? B0 + (size_t)r * K : B1 + (size_t)(r - 64) * K)
                           + t * BKF + c4 * 4;
            else      gb = B0 + (size_t)(n0 + r) * K + t * BKF + c4 * 4;
            cp16(smem_u32(dstB + r * LDA + c4 * 4), gb);
        }
        asm volatile("cp.async.commit_group;" ::: "memory");
    };

    stage(0, 0);

    for (int t = 0; t < NT; t++) {
        if (t + 1 < NT) {
            stage(t + 1, (t + 1) & 1);
            asm volatile("cp.async.wait_group 1;" ::: "memory");
        } else {
            asm volatile("cp.async.wait_group 0;" ::: "memory");
        }
        __syncthreads();

        const float* sA = sm + (t & 1) * 2 * TILE_F + (wm * 64) * LDA;
        const float* sB = sm + (t & 1) * 2 * TILE_F + TILE_F + (wn * 32) * LDA;

#pragma unroll
        for (int ks = 0; ks < 4; ks++) {
            uint32_t bf[4][2];
#pragma unroll
            for (int nt = 0; nt < 4; nt++) {
                const float* bp = sB + (nt * 8 + g) * LDA + ks * 8 + tig;
                bf[nt][0] = f2tf32(bp[0]);
                bf[nt][1] = f2tf32(bp[4]);
            }
            uint32_t af[4][4];
#pragma unroll
            for (int mt = 0; mt < 4; mt++) {
                const float* ap = sA + (mt * 16 + g) * LDA + ks * 8 + tig;
                af[mt][0] = f2tf32(ap[0]);
                af[mt][1] = f2tf32(ap[8 * LDA]);
                af[mt][2] = f2tf32(ap[4]);
                af[mt][3] = f2tf32(ap[8 * LDA + 4]);
            }
#pragma unroll
            for (int mt = 0; mt < 4; mt++)
#pragma unroll
                for (int nt = 0; nt < 4; nt++)
                    mma_tf32(acc[mt][nt][0], acc[mt][nt][1], acc[mt][nt][2], acc[mt][nt][3],
                             af[mt][0], af[mt][1], af[mt][2], af[mt][3],
                             bf[nt][0], bf[nt][1]);
        }
        __syncthreads();
    }

#pragma unroll
    for (int mt = 0; mt < 4; mt++) {
        const int row0 = m0 + wm * 64 + mt * 16 + g;
#pragma unroll
        for (int nt = 0; nt < 4; nt++) {
            const int colL = wn * 32 + nt * 8 + 2 * tig;
            if (dual) {
                float* dst = (colL < 64) ? C0 : C1;
                const int c = (colL < 64) ? colL : colL - 64;
                *(float2*)(dst + (size_t)row0 * 64 + c)       = make_float2(acc[mt][nt][0], acc[mt][nt][1]);
                *(float2*)(dst + (size_t)(row0 + 8) * 64 + c) = make_float2(acc[mt][nt][2], acc[mt][nt][3]);
            } else {
                const int col = n0 + colL;
                *(float2*)(C0 + (size_t)row0 * N + col)       = make_float2(acc[mt][nt][0], acc[mt][nt][1]);
                *(float2*)(C0 + (size_t)(row0 + 8) * N + col) = make_float2(acc[mt][nt][2], acc[mt][nt][3]);
            }
        }
    }
}

// ============================================================
// Flash attention with mma.sync tf32.
// Grid (T/128, NH), 256 threads (8 warps). Warp w owns rows
// [q0+16w, q0+16w+16), full D=64. K/V tiles of 64 keys via
// cp.async. P goes through warp-private smem.
// Strides: K=68 (frag bank 4g+tig), V=72 (frag bank 8tig+g),
// P=68 — all conflict-free for their fragment access patterns.
// ============================================================
#define SPK 68
#define SPV 72
#define SPP 68
#define ATT_SMEM ((64 * SPK + 64 * SPV + 128 * SPP) * 4)   // 70656 B

__global__ __launch_bounds__(256) void attn_mma(const float* __restrict__ Q,
                                                const float* __restrict__ Kg,
                                                const float* __restrict__ Vg,
                                                float* __restrict__ O) {
    extern __shared__ float sm[];
    float* Ksh = sm;                  // [64][SPK]
    float* Vsh = sm + 64 * SPK;       // [64][SPV]
    float* P   = sm + 64 * SPK + 64 * SPV;  // [128][SPP]

    const int h   = blockIdx.y;
    const int q0  = blockIdx.x * 128;
    const int tid = threadIdx.x;
    const int wid = tid >> 5;
    const int lane = tid & 31;
    const int g   = lane >> 2;
    const int tig = lane & 3;
    const float slope = exp2f(-0.25f * (float)(h + 1));

    // ---- stage Q tile (pre-scaled) into P region, then load A-fragments ----
#pragma unroll
    for (int u = 0; u < 8; u++) {
        int idx = u * 256 + tid;          // 0..2047 float4 slots (128 rows x 16)
        int r = idx >> 4, c4 = idx & 15;
        float4 v = *(const float4*)(Q + (size_t)(q0 + r) * EMB + h * HD + c4 * 4);
        v.x *= 0.125f; v.y *= 0.125f; v.z *= 0.125f; v.w *= 0.125f;
        *(float4*)(P + r * SPP + c4 * 4) = v;
    }
    __syncthreads();

    uint32_t qf[8][4];
    {
        const float* PW = P + wid * 16 * SPP;
#pragma unroll
        for (int ks = 0; ks < 8; ks++) {
            const int k = ks * 8 + tig;
            qf[ks][0] = f2tf32(PW[g * SPP + k]);
            qf[ks][1] = f2tf32(PW[(g + 8) * SPP + k]);
            qf[ks][2] = f2tf32(PW[g * SPP + k + 4]);
            qf[ks][3] = f2tf32(PW[(g + 8) * SPP + k + 4]);
        }
    }

    float oacc[8][4];
#pragma unroll
    for (int nt = 0; nt < 8; nt++)
#pragma unroll
        for (int r = 0; r < 4; r++) oacc[nt][r] = 0.f;

    float m0r = -1e30f, m1r = -1e30f;    // running max, rows g / g+8
    float l0 = 0.f, l1 = 0.f;
    const int i0 = q0 + wid * 16 + g;
    const int i1 = i0 + 8;
    float* PWm = P + (wid * 16 + g) * SPP;       // row g of this warp
    float* PWm8 = PWm + 8 * SPP;                 // row g+8

    for (int j0 = 0; j0 < q0 + 128; j0 += 64) {
        __syncthreads();   // previous tile fully consumed
        // stage K and V tiles (64 rows x 64 floats each)
#pragma unroll
        for (int u = 0; u < 4; u++) {
            int idx = u * 256 + tid;      // 0..1023
            int r = idx >> 4, c4 = idx & 15;
            cp16(smem_u32(Ksh + r * SPK + c4 * 4), Kg + (size_t)(j0 + r) * HD + c4 * 4);
            cp16(smem_u32(Vsh + r * SPV + c4 * 4), Vg + (size_t)(j0 + r) * HD + c4 * 4);
        }
        asm volatile("cp.async.commit_group;" ::: "memory");
        asm volatile("cp.async.wait_group 0;" ::: "memory");
        __syncthreads();

        // ---- S = Q @ K^T ----
        float sacc[8][4];
#pragma unroll
        for (int nt = 0; nt < 8; nt++)
#pragma unroll
            for (int r = 0; r < 4; r++) sacc[nt][r] = 0.f;

#pragma unroll
        for (int ks = 0; ks < 8; ks++) {
#pragma unroll
            for (int nt = 0; nt < 8; nt++) {
                const float* kp = Ksh + (nt * 8 + g) * SPK + ks * 8 + tig;
                uint32_t b0 = f2tf32(kp[0]);
                uint32_t b1 = f2tf32(kp[4]);
                mma_tf32(sacc[nt][0], sacc[nt][1], sacc[nt][2], sacc[nt][3],
                         qf[ks][0], qf[ks][1], qf[ks][2], qf[ks][3], b0, b1);
            }
        }

        // ---- ALiBi + causal mask, tile max ----
        float mx0 = -1e30f, mx1 = -1e30f;
#pragma unroll
        for (int nt = 0; nt < 8; nt++) {
            const int jb = j0 + nt * 8 + 2 * tig;
            float v0 = (jb     <= i0) ? fmaf(slope, (float)(jb     - i0), sacc[nt][0]) : -1e30f;
            float v1 = (jb + 1 <= i0) ? fmaf(slope, (float)(jb + 1 - i0), sacc[nt][1]) : -1e30f;
            float v2 = (jb     <= i1) ? fmaf(slope, (float)(jb     - i1), sacc[nt][2]) : -1e30f;
            float v3 = (jb + 1 <= i1) ? fmaf(slope, (float)(jb + 1 - i1), sacc[nt][3]) : -1e30f;
            sacc[nt][0] = v0; sacc[nt][1] = v1; sacc[nt][2] = v2; sacc[nt][3] = v3;
            mx0 = fmaxf(mx0, fmaxf(v0, v1));
            mx1 = fmaxf(mx1, fmaxf(v2, v3));
        }
        mx0 = fmaxf(mx0, __shfl_xor_sync(0xffffffffu, mx0, 1));
        mx0 = fmaxf(mx0, __shfl_xor_sync(0xffffffffu, mx0, 2));
        mx1 = fmaxf(mx1, __shfl_xor_sync(0xffffffffu, mx1, 1));
        mx1 = fmaxf(mx1, __shfl_xor_sync(0xffffffffu, mx1, 2));

        const float mn0 = fmaxf(m0r, mx0);
        const float mn1 = fmaxf(m1r, mx1);
        const float a0 = __expf(m0r - mn0);
        const float a1 = __expf(m1r - mn1);

        float ps0 = 0.f, ps1 = 0.f;
#pragma unroll
        for (int nt = 0; nt < 8; nt++) {
            float e0 = __expf(sacc[nt][0] - mn0);
            float e1 = __expf(sacc[nt][1] - mn0);
            float e2 = __expf(sacc[nt][2] - mn1);
            float e3 = __expf(sacc[nt][3] - mn1);
            ps0 += e0 + e1;
            ps1 += e2 + e3;
            const int col = nt * 8 + 2 * tig;
            *(float2*)(PWm  + col) = make_float2(e0, e1);
            *(float2*)(PWm8 + col) = make_float2(e2, e3);
        }
        ps0 += __shfl_xor_sync(0xffffffffu, ps0, 1);
        ps0 += __shfl_xor_sync(0xffffffffu, ps0, 2);
        ps1 += __shfl_xor_sync(0xffffffffu, ps1, 1);
        ps1 += __shfl_xor_sync(0xffffffffu, ps1, 2);
        l0 = l0 * a0 + ps0;
        l1 = l1 * a1 + ps1;
#pragma unroll
        for (int nt = 0; nt < 8; nt++) {
            oacc[nt][0] *= a0; oacc[nt][1] *= a0;
            oacc[nt][2] *= a1; oacc[nt][3] *= a1;
        }
        m0r = mn0; m1r = mn1;
        __syncwarp();

        // ---- O += P @ V ----
        const float* PW = P + wid * 16 * SPP;
#pragma unroll
        for (int ks = 0; ks < 8; ks++) {
            const int k = ks * 8 + tig;
            uint32_t pa0 = f2tf32(PW[g * SPP + k]);
            uint32_t pa1 = f2tf32(PW[(g + 8) * SPP + k]);
            uint32_t pa2 = f2tf32(PW[g * SPP + k + 4]);
            uint32_t pa3 = f2tf32(PW[(g + 8) * SPP + k + 4]);
#pragma unroll
            for (int nt = 0; nt < 8; nt++) {
                const float* vp = Vsh + (ks * 8 + tig) * SPV + nt * 8 + g;
                uint32_t b0 = f2tf32(vp[0]);
                uint32_t b1 = f2tf32(vp[4 * SPV]);
                mma_tf32(oacc[nt][0], oacc[nt][1], oacc[nt][2], oacc[nt][3],
                         pa0, pa1, pa2, pa3, b0, b1);
            }
        }
    }

    // ---- normalize + store ----
    const float inv0 = 1.0f / l0;
    const float inv1 = 1.0f / l1;
    const int row0 = q0 + wid * 16 + g;
#pragma unroll
    for (int nt = 0; nt < 8; nt++) {
        const int col = h * HD + nt * 8 + 2 * tig;
        *(float2*)(O + (size_t)row0 * EMB + col) =
            make_float2(oacc[nt][0] * inv0, oacc[nt][1] * inv0);
        *(float2*)(O + (size_t)(row0 + 8) * EMB + col) =
            make_float2(oacc[nt][2] * inv1, oacc[nt][3] * inv1);
    }
}

// ============================================================
// launch
// ============================================================
extern "C" void kernel_launch(void* const* d_in, const int* in_sizes, int n_in,
                              void* d_out, int out_size) {
    (void)in_sizes; (void)n_in; (void)out_size;
    const float* x  = (const float*)d_in[0];
    const float* Wq = (const float*)d_in[1];
    const float* Wk = (const float*)d_in[2];
    const float* Wv = (const float*)d_in[3];
    const float* Wo = (const float*)d_in[4];
    float* out = (float*)d_out;

    void *pQ, *pK, *pV, *pA;
    cudaGetSymbolAddress(&pQ, g_Q);
    cudaGetSymbolAddress(&pK, g_K);
    cudaGetSymbolAddress(&pV, g_V);
    cudaGetSymbolAddress(&pA, g_A);
    float* Qd = (float*)pQ;
    float* Kd = (float*)pK;
    float* Vd = (float*)pV;
    float* Ad = (float*)pA;

    cudaFuncSetAttribute(gemm_tf32mma, cudaFuncAttributeMaxDynamicSharedMemorySize, GEMM_SMEM);
    cudaFuncSetAttribute(attn_mma, cudaFuncAttributeMaxDynamicSharedMemorySize, ATT_SMEM);

    gemm_tf32mma<<<dim3(EMB / 128, T_SEQ / 128), 256, GEMM_SMEM>>>(
        x, Wq, nullptr, Qd, nullptr, EMB, EMB, 0);
    gemm_tf32mma<<<dim3(1, T_SEQ / 128), 256, GEMM_SMEM>>>(
        x, Wk, Wv, Kd, Vd, EMB, 128, 1);
    attn_mma<<<dim3(T_SEQ / 128, NH), 256, ATT_SMEM>>>(Qd, Kd, Vd, Ad);
    gemm_tf32mma<<<dim3(EMB / 128, T_SEQ / 128), 256, GEMM_SMEM>>>(
        Ad, Wo, nullptr, out, nullptr, EMB, EMB, 0);
}

// round 6
// speedup vs baseline: 4.8297x; 1.0622x over previous
#include <cuda_runtime.h>
#include <cstdint>

// Problem constants
#define T_SEQ 2048
#define EMB   2048
#define NH    32
#define HD    64

// -------- scratch (device globals; no allocation allowed) --------
__device__ float g_Q[T_SEQ * EMB];   // q projection [T, E] (pre-rounded, pre-scaled)
__device__ float g_K[T_SEQ * HD];    // k projection (pre-rounded)
__device__ float g_V[T_SEQ * HD];    // v projection (pre-rounded)
__device__ float g_A[T_SEQ * EMB];   // attention output (pre-rounded)
__device__ float g_x [T_SEQ * EMB];  // tf32-rounded x
__device__ float g_wq[EMB * EMB];    // tf32-rounded Wq
__device__ float g_wo[EMB * EMB];    // tf32-rounded Wo
__device__ float g_wk[HD * EMB];     // tf32-rounded Wk
__device__ float g_wv[HD * EMB];     // tf32-rounded Wv

// ============================================================
// helpers
// ============================================================
__device__ __forceinline__ uint32_t smem_u32(const void* p) {
    uint32_t a;
    asm("{ .reg .u64 t; cvta.to.shared.u64 t, %1; cvt.u32.u64 %0, t; }" : "=r"(a) : "l"(p));
    return a;
}
__device__ __forceinline__ uint32_t f2tf32(float x) {
    uint32_t r;
    asm("cvt.rna.tf32.f32 %0, %1;" : "=r"(r) : "f"(x));
    return r;
}
__device__ __forceinline__ float rnd(float x) { return __uint_as_float(f2tf32(x)); }
__device__ __forceinline__ void cp16(uint32_t dst, const void* src) {
    asm volatile("cp.async.cg.shared.global [%0], [%1], 16;" :: "r"(dst), "l"(src) : "memory");
}
__device__ __forceinline__ void mma_tf32(float& d0, float& d1, float& d2, float& d3,
                                         uint32_t a0, uint32_t a1, uint32_t a2, uint32_t a3,
                                         uint32_t b0, uint32_t b1) {
    asm volatile("mma.sync.aligned.m16n8k8.row.col.f32.tf32.tf32.f32 "
                 "{%0,%1,%2,%3}, {%4,%5,%6,%7}, {%8,%9}, {%0,%1,%2,%3};"
                 : "+f"(d0), "+f"(d1), "+f"(d2), "+f"(d3)
                 : "r"(a0), "r"(a1), "r"(a2), "r"(a3), "r"(b0), "r"(b1));
}

// ============================================================
// tf32 rounding pre-pass (grid-stride, float4)
// ============================================================
__global__ void round_pass(const float4* __restrict__ src, float4* __restrict__ dst, int n4) {
    for (int i = blockIdx.x * blockDim.x + threadIdx.x; i < n4; i += gridDim.x * blockDim.x) {
        float4 v = src[i];
        v.x = rnd(v.x); v.y = rnd(v.y); v.z = rnd(v.z); v.w = rnd(v.w);
        dst[i] = v;
    }
}

// ============================================================
// tf32 mma.sync GEMM:  C[M,N] = A[M,K] @ B[N,K]^T
// Inputs must be PRE-ROUNDED to tf32. No cvt in hot loop.
// do_round: epilogue rounds (acc*oscale) to tf32 before store.
// ============================================================
#define BKF 32
#define LDA 36
#define TILE_F (128 * LDA)
#define GEMM_SMEM (2 * 2 * TILE_F * 4)

__global__ __launch_bounds__(256, 2) void gemm_tf32mma(
    const float* __restrict__ A, const float* __restrict__ B0,
    const float* __restrict__ B1, float* __restrict__ C0,
    float* __restrict__ C1, int K, int N, int dual,
    int do_round, float oscale) {
    extern __shared__ float sm[];
    const int tid  = threadIdx.x;
    const int wid  = tid >> 5;
    const int lane = tid & 31;
    const int wm   = wid & 1;
    const int wn   = wid >> 1;
    const int m0   = blockIdx.y * 128;
    const int n0   = blockIdx.x * 128;
    const int g    = lane >> 2;
    const int tig  = lane & 3;

    float acc[4][4][4];
#pragma unroll
    for (int i = 0; i < 4; i++)
#pragma unroll
        for (int j = 0; j < 4; j++)
#pragma unroll
            for (int r = 0; r < 4; r++) acc[i][j][r] = 0.f;

    const int NT = K / BKF;

    auto stage = [&](int t, int b) {
        float* dstA = sm + b * 2 * TILE_F;
        float* dstB = dstA + TILE_F;
#pragma unroll
        for (int u = 0; u < 4; u++) {
            int idx = u * 256 + tid;
            int r = idx >> 3, c4 = idx & 7;
            cp16(smem_u32(dstA + r * LDA + c4 * 4),
                 A + (size_t)(m0 + r) * K + t * BKF + c4 * 4);
            const float* gb;
            if (dual) gb = (r < 64 ? B0 + (size_t)r * K : B1 + (size_t)(r - 64) * K)
                           + t * BKF + c4 * 4;
            else      gb = B0 + (size_t)(n0 + r) * K + t * BKF + c4 * 4;
            cp16(smem_u32(dstB + r * LDA + c4 * 4), gb);
        }
        asm volatile("cp.async.commit_group;" ::: "memory");
    };

    stage(0, 0);

    for (int t = 0; t < NT; t++) {
        if (t + 1 < NT) {
            stage(t + 1, (t + 1) & 1);
            asm volatile("cp.async.wait_group 1;" ::: "memory");
        } else {
            asm volatile("cp.async.wait_group 0;" ::: "memory");
        }
        __syncthreads();

        const float* sA = sm + (t & 1) * 2 * TILE_F + (wm * 64) * LDA;
        const float* sB = sm + (t & 1) * 2 * TILE_F + TILE_F + (wn * 32) * LDA;

#pragma unroll
        for (int ks = 0; ks < 4; ks++) {
            uint32_t bf[4][2];
#pragma unroll
            for (int nt = 0; nt < 4; nt++) {
                const float* bp = sB + (nt * 8 + g) * LDA + ks * 8 + tig;
                bf[nt][0] = __float_as_uint(bp[0]);
                bf[nt][1] = __float_as_uint(bp[4]);
            }
            uint32_t af[4][4];
#pragma unroll
            for (int mt = 0; mt < 4; mt++) {
                const float* ap = sA + (mt * 16 + g) * LDA + ks * 8 + tig;
                af[mt][0] = __float_as_uint(ap[0]);
                af[mt][1] = __float_as_uint(ap[8 * LDA]);
                af[mt][2] = __float_as_uint(ap[4]);
                af[mt][3] = __float_as_uint(ap[8 * LDA + 4]);
            }
#pragma unroll
            for (int mt = 0; mt < 4; mt++)
#pragma unroll
                for (int nt = 0; nt < 4; nt++)
                    mma_tf32(acc[mt][nt][0], acc[mt][nt][1], acc[mt][nt][2], acc[mt][nt][3],
                             af[mt][0], af[mt][1], af[mt][2], af[mt][3],
                             bf[nt][0], bf[nt][1]);
        }
        __syncthreads();
    }

#pragma unroll
    for (int mt = 0; mt < 4; mt++) {
        const int row0 = m0 + wm * 64 + mt * 16 + g;
#pragma unroll
        for (int nt = 0; nt < 4; nt++) {
            float v0 = acc[mt][nt][0] * oscale, v1 = acc[mt][nt][1] * oscale;
            float v2 = acc[mt][nt][2] * oscale, v3 = acc[mt][nt][3] * oscale;
            if (do_round) { v0 = rnd(v0); v1 = rnd(v1); v2 = rnd(v2); v3 = rnd(v3); }
            const int colL = wn * 32 + nt * 8 + 2 * tig;
            if (dual) {
                float* dst = (colL < 64) ? C0 : C1;
                const int c = (colL < 64) ? colL : colL - 64;
                *(float2*)(dst + (size_t)row0 * 64 + c)       = make_float2(v0, v1);
                *(float2*)(dst + (size_t)(row0 + 8) * 64 + c) = make_float2(v2, v3);
            } else {
                const int col = n0 + colL;
                *(float2*)(C0 + (size_t)row0 * N + col)       = make_float2(v0, v1);
                *(float2*)(C0 + (size_t)(row0 + 8) * N + col) = make_float2(v2, v3);
            }
        }
    }
}

// ============================================================
// Flash attention with mma.sync tf32. Q/K/V pre-rounded (Q also
// pre-scaled by D^-1/2). P rounded once at smem write. Output A
// written tf32-rounded for the final GEMM.
// ============================================================
#define SPK 68
#define SPV 72
#define SPP 68
#define ATT_SMEM ((64 * SPK + 64 * SPV + 128 * SPP) * 4)   // 70656 B

__global__ __launch_bounds__(256) void attn_mma(const float* __restrict__ Q,
                                                const float* __restrict__ Kg,
                                                const float* __restrict__ Vg,
                                                float* __restrict__ O) {
    extern __shared__ float sm[];
    float* Ksh = sm;                        // [64][SPK]
    float* Vsh = sm + 64 * SPK;             // [64][SPV]
    float* P   = sm + 64 * SPK + 64 * SPV;  // [128][SPP]

    const int h   = blockIdx.y;
    const int q0  = blockIdx.x * 128;
    const int tid = threadIdx.x;
    const int wid = tid >> 5;
    const int lane = tid & 31;
    const int g   = lane >> 2;
    const int tig = lane & 3;
    const float slope = exp2f(-0.25f * (float)(h + 1));

    // ---- stage Q tile into P region, then load A-fragments ----
#pragma unroll
    for (int u = 0; u < 8; u++) {
        int idx = u * 256 + tid;
        int r = idx >> 4, c4 = idx & 15;
        *(float4*)(P + r * SPP + c4 * 4) =
            *(const float4*)(Q + (size_t)(q0 + r) * EMB + h * HD + c4 * 4);
    }
    __syncthreads();

    uint32_t qf[8][4];
    {
        const float* PW = P + wid * 16 * SPP;
#pragma unroll
        for (int ks = 0; ks < 8; ks++) {
            const int k = ks * 8 + tig;
            qf[ks][0] = __float_as_uint(PW[g * SPP + k]);
            qf[ks][1] = __float_as_uint(PW[(g + 8) * SPP + k]);
            qf[ks][2] = __float_as_uint(PW[g * SPP + k + 4]);
            qf[ks][3] = __float_as_uint(PW[(g + 8) * SPP + k + 4]);
        }
    }

    float oacc[8][4];
#pragma unroll
    for (int nt = 0; nt < 8; nt++)
#pragma unroll
        for (int r = 0; r < 4; r++) oacc[nt][r] = 0.f;

    float m0r = -1e30f, m1r = -1e30f;
    float l0 = 0.f, l1 = 0.f;
    const int i0 = q0 + wid * 16 + g;
    const int i1 = i0 + 8;
    float* PWm  = P + (wid * 16 + g) * SPP;
    float* PWm8 = PWm + 8 * SPP;

    for (int j0 = 0; j0 < q0 + 128; j0 += 64) {
        __syncthreads();
#pragma unroll
        for (int u = 0; u < 4; u++) {
            int idx = u * 256 + tid;
            int r = idx >> 4, c4 = idx & 15;
            cp16(smem_u32(Ksh + r * SPK + c4 * 4), Kg + (size_t)(j0 + r) * HD + c4 * 4);
            cp16(smem_u32(Vsh + r * SPV + c4 * 4), Vg + (size_t)(j0 + r) * HD + c4 * 4);
        }
        asm volatile("cp.async.commit_group;" ::: "memory");
        asm volatile("cp.async.wait_group 0;" ::: "memory");
        __syncthreads();

        // ---- S = Q @ K^T ----
        float sacc[8][4];
#pragma unroll
        for (int nt = 0; nt < 8; nt++)
#pragma unroll
            for (int r = 0; r < 4; r++) sacc[nt][r] = 0.f;

#pragma unroll
        for (int ks = 0; ks < 8; ks++) {
#pragma unroll
            for (int nt = 0; nt < 8; nt++) {
                const float* kp = Ksh + (nt * 8 + g) * SPK + ks * 8 + tig;
                uint32_t b0 = __float_as_uint(kp[0]);
                uint32_t b1 = __float_as_uint(kp[4]);
                mma_tf32(sacc[nt][0], sacc[nt][1], sacc[nt][2], sacc[nt][3],
                         qf[ks][0], qf[ks][1], qf[ks][2], qf[ks][3], b0, b1);
            }
        }

        // ---- ALiBi + causal mask, tile max ----
        float mx0 = -1e30f, mx1 = -1e30f;
#pragma unroll
        for (int nt = 0; nt < 8; nt++) {
            const int jb = j0 + nt * 8 + 2 * tig;
            float v0 = (jb     <= i0) ? fmaf(slope, (float)(jb     - i0), sacc[nt][0]) : -1e30f;
            float v1 = (jb + 1 <= i0) ? fmaf(slope, (float)(jb + 1 - i0), sacc[nt][1]) : -1e30f;
            float v2 = (jb     <= i1) ? fmaf(slope, (float)(jb     - i1), sacc[nt][2]) : -1e30f;
            float v3 = (jb + 1 <= i1) ? fmaf(slope, (float)(jb + 1 - i1), sacc[nt][3]) : -1e30f;
            sacc[nt][0] = v0; sacc[nt][1] = v1; sacc[nt][2] = v2; sacc[nt][3] = v3;
            mx0 = fmaxf(mx0, fmaxf(v0, v1));
            mx1 = fmaxf(mx1, fmaxf(v2, v3));
        }
        mx0 = fmaxf(mx0, __shfl_xor_sync(0xffffffffu, mx0, 1));
        mx0 = fmaxf(mx0, __shfl_xor_sync(0xffffffffu, mx0, 2));
        mx1 = fmaxf(mx1, __shfl_xor_sync(0xffffffffu, mx1, 1));
        mx1 = fmaxf(mx1, __shfl_xor_sync(0xffffffffu, mx1, 2));

        const float mn0 = fmaxf(m0r, mx0);
        const float mn1 = fmaxf(m1r, mx1);
        const float a0 = __expf(m0r - mn0);
        const float a1 = __expf(m1r - mn1);

        float ps0 = 0.f, ps1 = 0.f;
#pragma unroll
        for (int nt = 0; nt < 8; nt++) {
            float e0 = __expf(sacc[nt][0] - mn0);
            float e1 = __expf(sacc[nt][1] - mn0);
            float e2 = __expf(sacc[nt][2] - mn1);
            float e3 = __expf(sacc[nt][3] - mn1);
            ps0 += e0 + e1;
            ps1 += e2 + e3;
            const int col = nt * 8 + 2 * tig;
            *(float2*)(PWm  + col) = make_float2(rnd(e0), rnd(e1));
            *(float2*)(PWm8 + col) = make_float2(rnd(e2), rnd(e3));
        }
        ps0 += __shfl_xor_sync(0xffffffffu, ps0, 1);
        ps0 += __shfl_xor_sync(0xffffffffu, ps0, 2);
        ps1 += __shfl_xor_sync(0xffffffffu, ps1, 1);
        ps1 += __shfl_xor_sync(0xffffffffu, ps1, 2);
        l0 = l0 * a0 + ps0;
        l1 = l1 * a1 + ps1;
#pragma unroll
        for (int nt = 0; nt < 8; nt++) {
            oacc[nt][0] *= a0; oacc[nt][1] *= a0;
            oacc[nt][2] *= a1; oacc[nt][3] *= a1;
        }
        m0r = mn0; m1r = mn1;
        __syncwarp();

        // ---- O += P @ V ----
        const float* PW = P + wid * 16 * SPP;
#pragma unroll
        for (int ks = 0; ks < 8; ks++) {
            const int k = ks * 8 + tig;
            uint32_t pa0 = __float_as_uint(PW[g * SPP + k]);
            uint32_t pa1 = __float_as_uint(PW[(g + 8) * SPP + k]);
            uint32_t pa2 = __float_as_uint(PW[g * SPP + k + 4]);
            uint32_t pa3 = __float_as_uint(PW[(g + 8) * SPP + k + 4]);
#pragma unroll
            for (int nt = 0; nt < 8; nt++) {
                const float* vp = Vsh + (ks * 8 + tig) * SPV + nt * 8 + g;
                uint32_t b0 = __float_as_uint(vp[0]);
                uint32_t b1 = __float_as_uint(vp[4 * SPV]);
                mma_tf32(oacc[nt][0], oacc[nt][1], oacc[nt][2], oacc[nt][3],
                         pa0, pa1, pa2, pa3, b0, b1);
            }
        }
    }

    // ---- normalize + store (rounded for the final GEMM) ----
    const float inv0 = 1.0f / l0;
    const float inv1 = 1.0f / l1;
    const int row0 = q0 + wid * 16 + g;
#pragma unroll
    for (int nt = 0; nt < 8; nt++) {
        const int col = h * HD + nt * 8 + 2 * tig;
        *(float2*)(O + (size_t)row0 * EMB + col) =
            make_float2(rnd(oacc[nt][0] * inv0), rnd(oacc[nt][1] * inv0));
        *(float2*)(O + (size_t)(row0 + 8) * EMB + col) =
            make_float2(rnd(oacc[nt][2] * inv1), rnd(oacc[nt][3] * inv1));
    }
}

// ============================================================
// launch
// ============================================================
extern "C" void kernel_launch(void* const* d_in, const int* in_sizes, int n_in,
                              void* d_out, int out_size) {
    (void)in_sizes; (void)n_in; (void)out_size;
    const float* x  = (const float*)d_in[0];
    const float* Wq = (const float*)d_in[1];
    const float* Wk = (const float*)d_in[2];
    const float* Wv = (const float*)d_in[3];
    const float* Wo = (const float*)d_in[4];
    float* out = (float*)d_out;

    void *pQ, *pK, *pV, *pA, *px, *pwq, *pwo, *pwk, *pwv;
    cudaGetSymbolAddress(&pQ, g_Q);
    cudaGetSymbolAddress(&pK, g_K);
    cudaGetSymbolAddress(&pV, g_V);
    cudaGetSymbolAddress(&pA, g_A);
    cudaGetSymbolAddress(&px, g_x);
    cudaGetSymbolAddress(&pwq, g_wq);
    cudaGetSymbolAddress(&pwo, g_wo);
    cudaGetSymbolAddress(&pwk, g_wk);
    cudaGetSymbolAddress(&pwv, g_wv);
    float* Qd = (float*)pQ;  float* Kd = (float*)pK;
    float* Vd = (float*)pV;  float* Ad = (float*)pA;
    float* xr = (float*)px;  float* wqr = (float*)pwq;
    float* wor = (float*)pwo; float* wkr = (float*)pwk; float* wvr = (float*)pwv;

    cudaFuncSetAttribute(gemm_tf32mma, cudaFuncAttributeMaxDynamicSharedMemorySize, GEMM_SMEM);
    cudaFuncSetAttribute(attn_mma, cudaFuncAttributeMaxDynamicSharedMemorySize, ATT_SMEM);

    // tf32 rounding pre-pass
    round_pass<<<592, 256>>>((const float4*)x,  (float4*)xr,  T_SEQ * EMB / 4);
    round_pass<<<592, 256>>>((const float4*)Wq, (float4*)wqr, EMB * EMB / 4);
    round_pass<<<592, 256>>>((const float4*)Wo, (float4*)wor, EMB * EMB / 4);
    round_pass<<<64,  256>>>((const float4*)Wk, (float4*)wkr, HD * EMB / 4);
    round_pass<<<64,  256>>>((const float4*)Wv, (float4*)wvr, HD * EMB / 4);

    // Q projection (epilogue: round + pre-scale by D^-1/2)
    gemm_tf32mma<<<dim3(EMB / 128, T_SEQ / 128), 256, GEMM_SMEM>>>(
        xr, wqr, nullptr, Qd, nullptr, EMB, EMB, 0, 1, 0.125f);
    // K/V projections fused (epilogue: round)
    gemm_tf32mma<<<dim3(1, T_SEQ / 128), 256, GEMM_SMEM>>>(
        xr, wkr, wvr, Kd, Vd, EMB, 128, 1, 1, 1.0f);
    // attention
    attn_mma<<<dim3(T_SEQ / 128, NH), 256, ATT_SMEM>>>(Qd, Kd, Vd, Ad);
    // output projection (plain fp32 epilogue)
    gemm_tf32mma<<<dim3(EMB / 128, T_SEQ / 128), 256, GEMM_SMEM>>>(
        Ad, wor, nullptr, out, nullptr, EMB, EMB, 0, 0, 1.0f);
}